// round 12
// baseline (speedup 1.0000x reference)
#include <cuda_runtime.h>
#include <math.h>
#include <float.h>

#define Bv 2
#define Nv 4096
#define Cv 64
#define TOPKv 24
#define MAXM 512

// Output layout (concatenated, float32):
// expected (B,N,3) | disp (B,3,N) | probs (B,N,N) | conf (B,N) | ent (B,N) | src_pos (B,N,3)
#define EXP_OFF   ((size_t)0)
#define DISP_OFF  ((size_t)(Bv*Nv*3))
#define PROBS_OFF ((size_t)(2*Bv*Nv*3))
#define CONF_OFF  (PROBS_OFF + (size_t)Bv*Nv*Nv)
#define ENT_OFF   (CONF_OFF + (size_t)Bv*Nv)
#define SP_OFF    (ENT_OFF + (size_t)Bv*Nv)

// Scratch (no cudaMalloc allowed)
__device__ float4 g_pack[Bv*Nv];            // (x, y, z, ||t||^2) per target node
__device__ float  g_tdT[(size_t)Bv*Nv*Cv];  // tgt_desc transposed: (B,N,64)
__device__ float  g_sdT[(size_t)Bv*Nv*Cv];  // src_desc transposed: (B,N,64)
__device__ float  g_adj[Bv*Nv];             // max(log softmax(tml)[...,0], -20) - 0.1*tgt_unc

__global__ void prep_kernel(const float* __restrict__ td,
                            const float* __restrict__ sd,
                            const float* __restrict__ tc,
                            const float* __restrict__ tml,
                            const float* __restrict__ tunc) {
    int idx = blockIdx.x * blockDim.x + threadIdx.x;
    if (idx < Bv * Cv * Nv) {
        int b = idx / (Cv * Nv);
        int r = idx - b * (Cv * Nv);
        int c = r / Nv;
        int j = r - c * Nv;
        size_t o = (((size_t)b * Nv + j) << 6) + c;
        g_tdT[o] = td[idx];
        g_sdT[o] = sd[idx];
    }
    if (idx < Bv * Nv) {
        int b = idx >> 12, j = idx & (Nv - 1);
        const float* t = tc + (size_t)b * 3 * Nv;
        float x = t[j], y = t[Nv + j], z = t[2 * Nv + j];
        g_pack[idx] = make_float4(x, y, z, x * x + y * y + z * z);
        float l0 = tml[(size_t)b * 2 * Nv + j];
        float l1 = tml[(size_t)b * 2 * Nv + Nv + j];
        // log(softmax[...,0]) = -log1p(exp(l1-l0)); overflow -> -inf -> clamped to -20
        g_adj[idx] = fmaxf(-log1pf(expf(l1 - l0)), -20.0f) - 0.1f * tunc[idx];
    }
}

__global__ void __launch_bounds__(256, 8)
matcher_kernel(const float* __restrict__ src_can,
               const float* __restrict__ src_ml,
               const float* __restrict__ src_unc,
               float* __restrict__ out) {
    __shared__ float s_sd[64];
    __shared__ int   s_idx[MAXM];
    __shared__ float s_d2a[MAXM];        // d2 of gathered pairs
    __shared__ float s_val[MAXM];        // score, then exp
    __shared__ float s_red[64];
    __shared__ int   s_redi[8];
    __shared__ int   s_cnt;

    const int tid  = threadIdx.x;
    const int lane = tid & 31;
    const int bi   = blockIdx.x;
    const int b    = bi >> 12;
    const int i    = bi & (Nv - 1);
    const int bN   = b * Nv;

    // Zero this row of probs output (coalesced; stores drain in background)
    float4* rowz = reinterpret_cast<float4*>(out + PROBS_OFF + (size_t)(bN + i) * Nv);
#pragma unroll
    for (int k = 0; k < 4; k++) rowz[tid + 256 * k] = make_float4(0.f, 0.f, 0.f, 0.f);

    // Source descriptor (coalesced from pre-transposed table)
    if (tid < 16)
        reinterpret_cast<float4*>(s_sd)[tid] =
            reinterpret_cast<const float4*>(g_sdT + ((size_t)(bN + i) << 6))[tid];
    if (tid == 0) s_cnt = 0;

    const float* sc = src_can + (size_t)b * 3 * Nv;
    const float sx = sc[i], sy = sc[Nv + i], sz = sc[2 * Nv + i];
    const float sn2 = sx * sx + sy * sy + sz * sz;

    const float4* __restrict__ pk = g_pack + bN;
    const float R2 = 0.45f * 0.45f;

    __syncthreads();   // s_cnt init visible before pass-1 leader atomics

    // Pass 1: 4096 squared distances, pure LDG->FMA->ballot (no STS).
    // Warp-aggregated gather of radius hits: (idx, d2) into smem lists.
#pragma unroll
    for (int k = 0; k < 16; k++) {
        int j = (k << 8) + tid;
        float4 t = pk[j];
        float dot = fmaf(sx, t.x, fmaf(sy, t.y, sz * t.z));
        float d2 = fmaf(-2.0f, dot, sn2 + t.w);
        bool hit = (d2 <= R2);
        unsigned mask = __ballot_sync(0xffffffffu, hit);
        if (mask) {
            int leader = __ffs(mask) - 1;
            int base = 0;
            if (lane == leader) base = atomicAdd(&s_cnt, __popc(mask));
            base = __shfl_sync(0xffffffffu, base, leader);
            if (hit) {
                int p = base + __popc(mask & ((1u << lane) - 1u));
                if (p < MAXM) { s_idx[p] = j; s_d2a[p] = d2; }
            }
        }
    }
    __syncthreads();
    int ctot = s_cnt;

    // Rare slow path (~3% of rows): tau = TOPK-th smallest d2 (recompute from pk).
    if (ctot < TOPKv) {
        float tau = R2;
        while (ctot < TOPKv) {
            float m = FLT_MAX; int c = 0;
#pragma unroll
            for (int k = 0; k < 16; k++) {
                int j = (k << 8) + tid;
                float4 t = pk[j];
                float dot = fmaf(sx, t.x, fmaf(sy, t.y, sz * t.z));
                float d2 = fmaf(-2.0f, dot, sn2 + t.w);
                if (d2 > tau) {
                    if (d2 < m) { m = d2; c = 1; }
                    else if (d2 == m) c++;
                }
            }
#pragma unroll
            for (int o = 16; o; o >>= 1) {
                float om = __shfl_xor_sync(0xffffffffu, m, o);
                int   oc = __shfl_xor_sync(0xffffffffu, c, o);
                if (om < m) { m = om; c = oc; }
                else if (om == m) c += oc;
            }
            if (lane == 0) { s_red[tid >> 5] = m; s_redi[tid >> 5] = c; }
            __syncthreads();
            float mm = s_red[0]; int cc = s_redi[0];
#pragma unroll
            for (int w = 1; w < 8; w++) {
                if (s_red[w] < mm) { mm = s_red[w]; cc = s_redi[w]; }
                else if (s_red[w] == mm) cc += s_redi[w];
            }
            __syncthreads();
            if (mm >= FLT_MAX) break;
            tau = mm; ctot += cc;
        }
        // gather extras in (R2, tau]
#pragma unroll
        for (int k = 0; k < 16; k++) {
            int j = (k << 8) + tid;
            float4 t = pk[j];
            float dot = fmaf(sx, t.x, fmaf(sy, t.y, sz * t.z));
            float d2 = fmaf(-2.0f, dot, sn2 + t.w);
            bool hit = (d2 > R2) && (d2 <= tau);
            unsigned mask = __ballot_sync(0xffffffffu, hit);
            if (mask) {
                int leader = __ffs(mask) - 1;
                int base = 0;
                if (lane == leader) base = atomicAdd(&s_cnt, __popc(mask));
                base = __shfl_sync(0xffffffffu, base, leader);
                if (hit) {
                    int p = base + __popc(mask & ((1u << lane) - 1u));
                    if (p < MAXM) { s_idx[p] = j; s_d2a[p] = d2; }
                }
            }
        }
        __syncthreads();
    }
    const int M = min(s_cnt, MAXM);

    // Scores: half-warp (16 lanes) per pair, float4 loads, 4 shuffles/pair.
    // Block-uniform trip count -> every lane executes every shuffle (safe).
    const float sunc = src_unc[bN + i];
    {
        const int half = tid >> 4;        // 0..15
        const int hl   = tid & 15;
        const float4 sd4 = reinterpret_cast<const float4*>(s_sd)[hl];
        const int T = (M + 15) >> 4;
        for (int t = 0; t < T; t++) {
            int p = (t << 4) + half;
            float part = 0.0f;
            int j = 0;
            if (p < M) {
                j = s_idx[p];
                float4 v = reinterpret_cast<const float4*>(
                               g_tdT + ((size_t)(bN + j) << 6))[hl];
                part = fmaf(v.x, sd4.x, fmaf(v.y, sd4.y,
                       fmaf(v.z, sd4.z, v.w * sd4.w)));
            }
#pragma unroll
            for (int o = 8; o; o >>= 1)
                part += __shfl_xor_sync(0xffffffffu, part, o, 16);
            if (hl == 0 && p < M) {
                float dist = sqrtf(fmaxf(s_d2a[p], 1e-12f));
                s_val[p] = part - dist - 0.1f * sunc + g_adj[bN + j];
            }
        }
    }
    __syncthreads();

    // Softmax over the sparse allowed set (disallowed entries underflow to exact 0
    // in the reference as well: exp(-1e4/0.07) == 0 in fp32)
    // Round 1: block max
    float lm = -FLT_MAX;
    for (int p = tid; p < M; p += 256) lm = fmaxf(lm, s_val[p]);
#pragma unroll
    for (int o = 16; o; o >>= 1) lm = fmaxf(lm, __shfl_xor_sync(0xffffffffu, lm, o));
    if (lane == 0) s_red[56 + (tid >> 5)] = lm;
    __syncthreads();
    float mx = s_red[56];
#pragma unroll
    for (int w = 1; w < 8; w++) mx = fmaxf(mx, s_red[56 + w]);

    // Round 2: one fused round for (Z, eu, e0, e1, e2, em)
    const float invT = 1.0f / 0.07f;
    const float step = 2.0f / 15.0f;
    float Z = 0.f, eu = 0.f, e0 = 0.f, e1 = 0.f, e2 = 0.f, em = 0.f;
    for (int p = tid; p < M; p += 256) {
        float u = (s_val[p] - mx) * invT;
        float e = __expf(u);
        s_val[p] = e;
        Z += e; eu += e * u; em = fmaxf(em, e);
        int j = s_idx[p];
        float c0 = (float)(j >> 8) * step - 1.0f;
        float c1 = (float)((j >> 4) & 15) * step - 1.0f;
        float c2 = (float)(j & 15) * step - 1.0f;
        e0 += e * c0; e1 += e * c1; e2 += e * c2;
    }
#pragma unroll
    for (int o = 16; o; o >>= 1) {
        Z  += __shfl_xor_sync(0xffffffffu, Z, o);
        eu += __shfl_xor_sync(0xffffffffu, eu, o);
        e0 += __shfl_xor_sync(0xffffffffu, e0, o);
        e1 += __shfl_xor_sync(0xffffffffu, e1, o);
        e2 += __shfl_xor_sync(0xffffffffu, e2, o);
        em  = fmaxf(em, __shfl_xor_sync(0xffffffffu, em, o));
    }
    if (lane == 0) {
        int base = (tid >> 5) * 6;               // [0..47], disjoint from [56..63]
        s_red[base + 0] = Z;  s_red[base + 1] = eu; s_red[base + 2] = e0;
        s_red[base + 3] = e1; s_red[base + 4] = e2; s_red[base + 5] = em;
    }
    __syncthreads();
    // lanes 0..5 of every warp each reduce one quantity over the 8 warps
    float acc = 0.f;
    if (lane < 5) {
#pragma unroll
        for (int w = 0; w < 8; w++) acc += s_red[w * 6 + lane];
    } else if (lane == 5) {
        acc = s_red[5];
#pragma unroll
        for (int w = 1; w < 8; w++) acc = fmaxf(acc, s_red[w * 6 + 5]);
    }
    float rZ  = __shfl_sync(0xffffffffu, acc, 0);
    float reu = __shfl_sync(0xffffffffu, acc, 1);
    float re0 = __shfl_sync(0xffffffffu, acc, 2);
    float re1 = __shfl_sync(0xffffffffu, acc, 3);
    float re2 = __shfl_sync(0xffffffffu, acc, 4);
    float rem = __shfl_sync(0xffffffffu, acc, 5);

    float invZ = 1.0f / rZ;

    // Direct sparse scatter (row already zeroed)
    float* rowp = out + PROBS_OFF + (size_t)(bN + i) * Nv;
    for (int p = tid; p < M; p += 256) rowp[s_idx[p]] = s_val[p] * invZ;

    if (tid == 0) {
        float Ex0 = re0 * invZ, Ex1 = re1 * invZ, Ex2 = re2 * invZ;
        float p0 = (float)(i >> 8) * step - 1.0f;
        float p1 = (float)((i >> 4) & 15) * step - 1.0f;
        float p2 = (float)(i & 15) * step - 1.0f;
        size_t ri = (size_t)(bN + i);
        out[EXP_OFF + ri * 3 + 0] = Ex0;
        out[EXP_OFF + ri * 3 + 1] = Ex1;
        out[EXP_OFF + ri * 3 + 2] = Ex2;
        out[DISP_OFF + (size_t)b * 3 * Nv + 0 * Nv + i] = Ex0 - p0;
        out[DISP_OFF + (size_t)b * 3 * Nv + 1 * Nv + i] = Ex1 - p1;
        out[DISP_OFF + (size_t)b * 3 * Nv + 2 * Nv + i] = Ex2 - p2;
        float l0 = src_ml[(size_t)b * 2 * Nv + i];
        float l1 = src_ml[(size_t)b * 2 * Nv + Nv + i];
        float smatch = 1.0f / (1.0f + __expf(l1 - l0));
        out[CONF_OFF + ri] = rem * invZ * smatch;
        // ent = -sum p log p = logZ - (sum e*u)/Z   with u = (s - max)/T
        out[ENT_OFF + ri] = __logf(rZ) - reu * invZ;
        out[SP_OFF + ri * 3 + 0] = p0;
        out[SP_OFF + ri * 3 + 1] = p1;
        out[SP_OFF + ri * 3 + 2] = p2;
    }
}

extern "C" void kernel_launch(void* const* d_in, const int* in_sizes, int n_in,
                              void* d_out, int out_size) {
    const float* src_can  = (const float*)d_in[0];
    const float* tgt_can  = (const float*)d_in[1];
    const float* src_desc = (const float*)d_in[2];
    const float* tgt_desc = (const float*)d_in[3];
    const float* src_ml   = (const float*)d_in[4];
    const float* tgt_ml   = (const float*)d_in[5];
    const float* src_unc  = (const float*)d_in[6];
    const float* tgt_unc  = (const float*)d_in[7];
    float* out = (float*)d_out;

    prep_kernel<<<(Bv * Cv * Nv + 255) / 256, 256>>>(tgt_desc, src_desc, tgt_can,
                                                     tgt_ml, tgt_unc);
    matcher_kernel<<<Bv * Nv, 256>>>(src_can, src_ml, src_unc, out);
}

// round 13
// speedup vs baseline: 1.3265x; 1.3265x over previous
#include <cuda_runtime.h>
#include <math.h>
#include <float.h>

#define Bv 2
#define Nv 4096
#define Cv 64
#define TOPKv 24
#define MAXM 512

// Output layout (concatenated, float32):
// expected (B,N,3) | disp (B,3,N) | probs (B,N,N) | conf (B,N) | ent (B,N) | src_pos (B,N,3)
#define EXP_OFF   ((size_t)0)
#define DISP_OFF  ((size_t)(Bv*Nv*3))
#define PROBS_OFF ((size_t)(2*Bv*Nv*3))
#define CONF_OFF  (PROBS_OFF + (size_t)Bv*Nv*Nv)
#define ENT_OFF   (CONF_OFF + (size_t)Bv*Nv)
#define SP_OFF    (ENT_OFF + (size_t)Bv*Nv)

// Scratch (no cudaMalloc allowed)
__device__ float4 g_pack[Bv*Nv];            // (x, y, z, ||t||^2) per target node
__device__ float  g_tdT[(size_t)Bv*Nv*Cv];  // tgt_desc transposed: (B,N,64)
__device__ float  g_sdT[(size_t)Bv*Nv*Cv];  // src_desc transposed: (B,N,64)
__device__ float  g_adj[Bv*Nv];             // max(log softmax(tml)[...,0], -20) - 0.1*tgt_unc

__global__ void prep_kernel(const float* __restrict__ td,
                            const float* __restrict__ sd,
                            const float* __restrict__ tc,
                            const float* __restrict__ tml,
                            const float* __restrict__ tunc) {
    int idx = blockIdx.x * blockDim.x + threadIdx.x;
    if (idx < Bv * Cv * Nv) {
        int b = idx / (Cv * Nv);
        int r = idx - b * (Cv * Nv);
        int c = r / Nv;
        int j = r - c * Nv;
        size_t o = (((size_t)b * Nv + j) << 6) + c;
        g_tdT[o] = td[idx];
        g_sdT[o] = sd[idx];
    }
    if (idx < Bv * Nv) {
        int b = idx >> 12, j = idx & (Nv - 1);
        const float* t = tc + (size_t)b * 3 * Nv;
        float x = t[j], y = t[Nv + j], z = t[2 * Nv + j];
        g_pack[idx] = make_float4(x, y, z, x * x + y * y + z * z);
        float l0 = tml[(size_t)b * 2 * Nv + j];
        float l1 = tml[(size_t)b * 2 * Nv + Nv + j];
        // log(softmax[...,0]) = -log1p(exp(l1-l0)); overflow -> -inf -> clamped to -20
        g_adj[idx] = fmaxf(-log1pf(expf(l1 - l0)), -20.0f) - 0.1f * tunc[idx];
    }
}

__global__ void __launch_bounds__(256, 7)
matcher_kernel(const float* __restrict__ src_can,
               const float* __restrict__ src_ml,
               const float* __restrict__ src_unc,
               float* __restrict__ out) {
    __shared__ float s_d2[Nv];            // 16 KB: all squared distances
    __shared__ float s_sd[64];
    __shared__ int   s_idx[MAXM];
    __shared__ float s_val[MAXM];
    __shared__ float s_red[64];
    __shared__ int   s_redi[8];
    __shared__ int   s_cnt;

    const int tid  = threadIdx.x;
    const int lane = tid & 31;
    const int bi   = blockIdx.x;
    const int b    = bi >> 12;
    const int i    = bi & (Nv - 1);
    const int bN   = b * Nv;

    // Zero this row of probs output (coalesced; stores drain in background)
    float4* rowz = reinterpret_cast<float4*>(out + PROBS_OFF + (size_t)(bN + i) * Nv);
#pragma unroll
    for (int k = 0; k < 4; k++) rowz[tid + 256 * k] = make_float4(0.f, 0.f, 0.f, 0.f);

    // Source descriptor (coalesced from pre-transposed table)
    if (tid < 16)
        reinterpret_cast<float4*>(s_sd)[tid] =
            reinterpret_cast<const float4*>(g_sdT + ((size_t)(bN + i) << 6))[tid];
    if (tid == 0) s_cnt = 0;

    const float* sc = src_can + (size_t)b * 3 * Nv;
    const float sx = sc[i], sy = sc[Nv + i], sz = sc[2 * Nv + i];
    const float sn2 = sx * sx + sy * sy + sz * sz;

    const float4* __restrict__ pk = g_pack + bN;
    const float R2 = 0.45f * 0.45f;

    __syncthreads();   // s_cnt init visible before gather atomics

    // Pass 1: all 4096 squared distances -> smem, radius hits -> register bitmask.
    // Pure LDG.128 / FMA / STS / predicated-OR stream: no ballot, no branch,
    // so ptxas can front-batch the 16 loads (MLP preserved).
    unsigned hm = 0;
#pragma unroll
    for (int k = 0; k < 16; k++) {
        int j = (k << 8) + tid;
        float4 t = pk[j];
        float dot = fmaf(sx, t.x, fmaf(sy, t.y, sz * t.z));
        float d2 = fmaf(-2.0f, dot, sn2 + t.w);
        s_d2[j] = d2;
        if (d2 <= R2) hm |= (1u << k);
    }

    // Gather: only threads owning hits (~30 per block) touch the atomic.
    if (hm) {
        int base = atomicAdd(&s_cnt, __popc(hm));
        while (hm) {
            int k = __ffs(hm) - 1;
            hm &= hm - 1;
            if (base < MAXM) s_idx[base] = (k << 8) + tid;
            base++;
        }
    }
    __syncthreads();
    int ctot = s_cnt;

    // tau = max(R2, TOPK-th smallest d2). Rare loop (~3% of rows), reads smem.
    if (ctot < TOPKv) {
        float tau = R2;
        while (ctot < TOPKv) {
            float m = FLT_MAX; int c = 0;
#pragma unroll
            for (int k = 0; k < 16; k++) {
                float v = s_d2[(k << 8) + tid];
                if (v > tau) {
                    if (v < m) { m = v; c = 1; }
                    else if (v == m) c++;
                }
            }
#pragma unroll
            for (int o = 16; o; o >>= 1) {
                float om = __shfl_xor_sync(0xffffffffu, m, o);
                int   oc = __shfl_xor_sync(0xffffffffu, c, o);
                if (om < m) { m = om; c = oc; }
                else if (om == m) c += oc;
            }
            if (lane == 0) { s_red[tid >> 5] = m; s_redi[tid >> 5] = c; }
            __syncthreads();
            float mm = s_red[0]; int cc = s_redi[0];
#pragma unroll
            for (int w = 1; w < 8; w++) {
                if (s_red[w] < mm) { mm = s_red[w]; cc = s_redi[w]; }
                else if (s_red[w] == mm) cc += s_redi[w];
            }
            __syncthreads();
            if (mm >= FLT_MAX) break;
            tau = mm; ctot += cc;
        }
        // gather extras in (R2, tau] (rare; plain divergent atomics are fine)
#pragma unroll
        for (int k = 0; k < 16; k++) {
            int j = (k << 8) + tid;
            float v = s_d2[j];
            if (v > R2 && v <= tau) {
                int p = atomicAdd(&s_cnt, 1);
                if (p < MAXM) s_idx[p] = j;
            }
        }
        __syncthreads();
    }
    const int M = min(s_cnt, MAXM);

    // Scores: half-warp (16 lanes) per pair, float4 loads, 4 shuffles/pair.
    // Block-uniform trip count -> every lane executes every shuffle (safe).
    const float sunc = src_unc[bN + i];
    {
        const int half = tid >> 4;        // 0..15
        const int hl   = tid & 15;
        const float4 sd4 = reinterpret_cast<const float4*>(s_sd)[hl];
        const int T = (M + 15) >> 4;
        for (int t = 0; t < T; t++) {
            int p = (t << 4) + half;
            float part = 0.0f;
            int j = 0;
            if (p < M) {
                j = s_idx[p];
                float4 v = reinterpret_cast<const float4*>(
                               g_tdT + ((size_t)(bN + j) << 6))[hl];
                part = fmaf(v.x, sd4.x, fmaf(v.y, sd4.y,
                       fmaf(v.z, sd4.z, v.w * sd4.w)));
            }
#pragma unroll
            for (int o = 8; o; o >>= 1)
                part += __shfl_xor_sync(0xffffffffu, part, o, 16);
            if (hl == 0 && p < M) {
                float dist = sqrtf(fmaxf(s_d2[j], 1e-12f));
                s_val[p] = part - dist - 0.1f * sunc + g_adj[bN + j];
            }
        }
    }
    __syncthreads();

    // Softmax over the sparse allowed set (disallowed entries underflow to exact 0
    // in the reference as well: exp(-1e4/0.07) == 0 in fp32)
    // Round 1: block max
    float lm = -FLT_MAX;
    for (int p = tid; p < M; p += 256) lm = fmaxf(lm, s_val[p]);
#pragma unroll
    for (int o = 16; o; o >>= 1) lm = fmaxf(lm, __shfl_xor_sync(0xffffffffu, lm, o));
    if (lane == 0) s_red[56 + (tid >> 5)] = lm;
    __syncthreads();
    float mx = s_red[56];
#pragma unroll
    for (int w = 1; w < 8; w++) mx = fmaxf(mx, s_red[56 + w]);

    // Round 2: one fused round for (Z, eu, e0, e1, e2, em)
    const float invT = 1.0f / 0.07f;
    const float step = 2.0f / 15.0f;
    float Z = 0.f, eu = 0.f, e0 = 0.f, e1 = 0.f, e2 = 0.f, em = 0.f;
    for (int p = tid; p < M; p += 256) {
        float u = (s_val[p] - mx) * invT;
        float e = __expf(u);
        s_val[p] = e;
        Z += e; eu += e * u; em = fmaxf(em, e);
        int j = s_idx[p];
        float c0 = (float)(j >> 8) * step - 1.0f;
        float c1 = (float)((j >> 4) & 15) * step - 1.0f;
        float c2 = (float)(j & 15) * step - 1.0f;
        e0 += e * c0; e1 += e * c1; e2 += e * c2;
    }
#pragma unroll
    for (int o = 16; o; o >>= 1) {
        Z  += __shfl_xor_sync(0xffffffffu, Z, o);
        eu += __shfl_xor_sync(0xffffffffu, eu, o);
        e0 += __shfl_xor_sync(0xffffffffu, e0, o);
        e1 += __shfl_xor_sync(0xffffffffu, e1, o);
        e2 += __shfl_xor_sync(0xffffffffu, e2, o);
        em  = fmaxf(em, __shfl_xor_sync(0xffffffffu, em, o));
    }
    if (lane == 0) {
        int base = (tid >> 5) * 6;               // [0..47], disjoint from [56..63]
        s_red[base + 0] = Z;  s_red[base + 1] = eu; s_red[base + 2] = e0;
        s_red[base + 3] = e1; s_red[base + 4] = e2; s_red[base + 5] = em;
    }
    __syncthreads();
    // lanes 0..5 of every warp each reduce one quantity over the 8 warps
    float acc = 0.f;
    if (lane < 5) {
#pragma unroll
        for (int w = 0; w < 8; w++) acc += s_red[w * 6 + lane];
    } else if (lane == 5) {
        acc = s_red[5];
#pragma unroll
        for (int w = 1; w < 8; w++) acc = fmaxf(acc, s_red[w * 6 + 5]);
    }
    float rZ  = __shfl_sync(0xffffffffu, acc, 0);
    float reu = __shfl_sync(0xffffffffu, acc, 1);
    float re0 = __shfl_sync(0xffffffffu, acc, 2);
    float re1 = __shfl_sync(0xffffffffu, acc, 3);
    float re2 = __shfl_sync(0xffffffffu, acc, 4);
    float rem = __shfl_sync(0xffffffffu, acc, 5);

    float invZ = 1.0f / rZ;

    // Direct sparse scatter (row already zeroed)
    float* rowp = out + PROBS_OFF + (size_t)(bN + i) * Nv;
    for (int p = tid; p < M; p += 256) rowp[s_idx[p]] = s_val[p] * invZ;

    if (tid == 0) {
        float Ex0 = re0 * invZ, Ex1 = re1 * invZ, Ex2 = re2 * invZ;
        float p0 = (float)(i >> 8) * step - 1.0f;
        float p1 = (float)((i >> 4) & 15) * step - 1.0f;
        float p2 = (float)(i & 15) * step - 1.0f;
        size_t ri = (size_t)(bN + i);
        out[EXP_OFF + ri * 3 + 0] = Ex0;
        out[EXP_OFF + ri * 3 + 1] = Ex1;
        out[EXP_OFF + ri * 3 + 2] = Ex2;
        out[DISP_OFF + (size_t)b * 3 * Nv + 0 * Nv + i] = Ex0 - p0;
        out[DISP_OFF + (size_t)b * 3 * Nv + 1 * Nv + i] = Ex1 - p1;
        out[DISP_OFF + (size_t)b * 3 * Nv + 2 * Nv + i] = Ex2 - p2;
        float l0 = src_ml[(size_t)b * 2 * Nv + i];
        float l1 = src_ml[(size_t)b * 2 * Nv + Nv + i];
        float smatch = 1.0f / (1.0f + __expf(l1 - l0));
        out[CONF_OFF + ri] = rem * invZ * smatch;
        // ent = -sum p log p = logZ - (sum e*u)/Z   with u = (s - max)/T
        out[ENT_OFF + ri] = __logf(rZ) - reu * invZ;
        out[SP_OFF + ri * 3 + 0] = p0;
        out[SP_OFF + ri * 3 + 1] = p1;
        out[SP_OFF + ri * 3 + 2] = p2;
    }
}

extern "C" void kernel_launch(void* const* d_in, const int* in_sizes, int n_in,
                              void* d_out, int out_size) {
    const float* src_can  = (const float*)d_in[0];
    const float* tgt_can  = (const float*)d_in[1];
    const float* src_desc = (const float*)d_in[2];
    const float* tgt_desc = (const float*)d_in[3];
    const float* src_ml   = (const float*)d_in[4];
    const float* tgt_ml   = (const float*)d_in[5];
    const float* src_unc  = (const float*)d_in[6];
    const float* tgt_unc  = (const float*)d_in[7];
    float* out = (float*)d_out;

    prep_kernel<<<(Bv * Cv * Nv + 255) / 256, 256>>>(tgt_desc, src_desc, tgt_can,
                                                     tgt_ml, tgt_unc);
    matcher_kernel<<<Bv * Nv, 256>>>(src_can, src_ml, src_unc, out);
}